// round 2
// baseline (speedup 1.0000x reference)
#include <cuda_runtime.h>

// Problem constants (fixed by setup_inputs)
#define S_LEN 4096
#define BATCH 8
#define DIM 1024
#define D4 (DIM / 4)          // 256 float4 per row
#define SPLIT 49
#define SCALE 32.0f           // sqrt(1024)

// Elementwise blocks (blockIdx.x < S_LEN): block = token t, thread = float4
// lane d. pe[t,d] loaded once into registers; all 8 emb loads issued
// back-to-back (MLP=8) before the stores.
//
// Doc block (blockIdx.x == S_LEN): 8 warps, warp w owns batch column w.
// Ballot-bitmask inclusive popc-scan, then zero positions immediately
// preceding a split token.
__global__ __launch_bounds__(256, 4)   // allow up to 64 regs: MLP needs them
void pe_fused_kernel(const float4* __restrict__ emb,
                     const int*    __restrict__ src,
                     const float4* __restrict__ pe,
                     float4*       __restrict__ out,
                     float*        __restrict__ doc)
{
    const int blk = blockIdx.x;

    if (blk < S_LEN) {
        const int t = blk;
        const int d = threadIdx.x;           // 0..255
        const float4 p = pe[t * D4 + d];

        // Batch all 8 loads first — independent LDG.128s in flight.
        float4 e[BATCH];
        #pragma unroll
        for (int b = 0; b < BATCH; b++)
            e[b] = emb[(t * BATCH + b) * D4 + d];

        #pragma unroll
        for (int b = 0; b < BATCH; b++) {
            float4 o;
            o.x = fmaf(e[b].x, SCALE, p.x);
            o.y = fmaf(e[b].y, SCALE, p.y);
            o.z = fmaf(e[b].z, SCALE, p.z);
            o.w = fmaf(e[b].w, SCALE, p.w);
            out[(t * BATCH + b) * D4 + d] = o;
        }
        return;
    }

    // ---- doc scan block ----
    __shared__ unsigned words[BATCH * 128];  // 4096 bits per column

    const int warp = threadIdx.x >> 5;       // batch column 0..7
    const int lane = threadIdx.x & 31;

    // Pass 1: build flag bitmasks
    #pragma unroll 4
    for (int c = 0; c < 128; c++) {
        const int t = c * 32 + lane;
        const int v = __ldg(&src[t * BATCH + warp]);
        unsigned m = __ballot_sync(0xFFFFFFFFu, v == SPLIT);
        if (lane == 0) words[warp * 128 + c] = m;
    }
    __syncwarp();

    // Pass 2: inclusive scan + m_next zeroing
    int carry = 0;
    const unsigned le_mask = 0xFFFFFFFFu >> (31 - lane);
    for (int c = 0; c < 128; c++) {
        const unsigned m = words[warp * 128 + c];
        const int t = c * 32 + lane;
        const int incl = carry + __popc(m & le_mask);

        unsigned next_bit;
        if (lane < 31)
            next_bit = (m >> (lane + 1)) & 1u;
        else
            next_bit = (c < 127) ? (words[warp * 128 + c + 1] & 1u) : 0u;

        doc[t * BATCH + warp] = next_bit ? 0.0f : (float)incl;
        carry += __popc(m);
    }
}

extern "C" void kernel_launch(void* const* d_in, const int* in_sizes, int n_in,
                              void* d_out, int out_size)
{
    const float* emb = (const float*)d_in[0];   // [S, B, DIM] f32
    const int*   src = (const int*)  d_in[1];   // [S, B, 1]   i32
    const float* pe  = (const float*)d_in[2];   // [5000, 1, DIM] f32

    float* out = (float*)d_out;                  // first in_sizes[0] floats
    float* doc = out + (size_t)in_sizes[0];      // then S*B floats

    pe_fused_kernel<<<S_LEN + 1, 256>>>(
        (const float4*)emb, src, (const float4*)pe,
        (float4*)out, doc);
}

// round 3
// speedup vs baseline: 1.6650x; 1.6650x over previous
#include <cuda_runtime.h>

// Problem constants (fixed by setup_inputs)
#define S_LEN 4096
#define BATCH 8
#define DIM 1024
#define D4 (DIM / 4)          // 256 float4 per row
#define SPLIT 49
#define SCALE 32.0f           // sqrt(1024)

// Grid = 1184 blocks = exactly one wave on 148 SMs at 8 CTAs/SM.
//   blockIdx 0           : doc segmented-count scan (runs in first wave,
//                          fully overlapped with the streaming work)
//   blockIdx 1..1183     : grid-stride over tokens t = (bid-1) + k*1183
//
// Per token: thread d holds pe[t,d] in registers, loops b=0..7 doing
// ldcs(emb) -> fma -> stcs(out). Streaming hints keep pe resident in L2.
#define EW_BLOCKS 1183

__global__ __launch_bounds__(256, 8)
void pe_fused_kernel(const float4* __restrict__ emb,
                     const int*    __restrict__ src,
                     const float4* __restrict__ pe,
                     float4*       __restrict__ out,
                     float*        __restrict__ doc)
{
    const int blk = blockIdx.x;

    if (blk > 0) {
        const int d = threadIdx.x;           // 0..255
        for (int t = blk - 1; t < S_LEN; t += EW_BLOCKS) {
            const float4 p = __ldg(&pe[t * D4 + d]);
            #pragma unroll
            for (int b = 0; b < BATCH; b++) {
                const int idx = (t * BATCH + b) * D4 + d;
                float4 e = __ldcs(&emb[idx]);
                float4 o;
                o.x = fmaf(e.x, SCALE, p.x);
                o.y = fmaf(e.y, SCALE, p.y);
                o.z = fmaf(e.z, SCALE, p.z);
                o.w = fmaf(e.w, SCALE, p.w);
                __stcs(&out[idx], o);
            }
        }
        return;
    }

    // ---- doc scan block (blockIdx 0, first wave) ----
    __shared__ unsigned words[BATCH * 128];  // 4096 bits per column

    const int warp = threadIdx.x >> 5;       // batch column 0..7
    const int lane = threadIdx.x & 31;

    // Pass 1: build flag bitmasks (independent iterations, unrolled for MLP)
    #pragma unroll 8
    for (int c = 0; c < 128; c++) {
        const int t = c * 32 + lane;
        const int v = __ldg(&src[t * BATCH + warp]);
        unsigned m = __ballot_sync(0xFFFFFFFFu, v == SPLIT);
        if (lane == 0) words[warp * 128 + c] = m;
    }
    __syncwarp();

    // Pass 2: inclusive popc-scan with carry; zero positions whose next
    // position is a split token.
    int carry = 0;
    const unsigned le_mask = 0xFFFFFFFFu >> (31 - lane);
    for (int c = 0; c < 128; c++) {
        const unsigned m = words[warp * 128 + c];
        const int t = c * 32 + lane;
        const int incl = carry + __popc(m & le_mask);

        unsigned next_bit;
        if (lane < 31)
            next_bit = (m >> (lane + 1)) & 1u;
        else
            next_bit = (c < 127) ? (words[warp * 128 + c + 1] & 1u) : 0u;

        doc[t * BATCH + warp] = next_bit ? 0.0f : (float)incl;
        carry += __popc(m);
    }
}

extern "C" void kernel_launch(void* const* d_in, const int* in_sizes, int n_in,
                              void* d_out, int out_size)
{
    const float* emb = (const float*)d_in[0];   // [S, B, DIM] f32
    const int*   src = (const int*)  d_in[1];   // [S, B, 1]   i32
    const float* pe  = (const float*)d_in[2];   // [5000, 1, DIM] f32

    float* out = (float*)d_out;                  // first in_sizes[0] floats
    float* doc = out + (size_t)in_sizes[0];      // then S*B floats

    pe_fused_kernel<<<EW_BLOCKS + 1, 256>>>(
        (const float4*)emb, src, (const float4*)pe,
        (float4*)out, doc);
}

// round 4
// speedup vs baseline: 1.8160x; 1.0907x over previous
#include <cuda_runtime.h>

// Problem constants (fixed by setup_inputs)
#define S_LEN 4096
#define BATCH 8
#define DIM 1024
#define D4 (DIM / 4)          // 256 float4 per row
#define SPLIT 49
#define SCALE 32.0f           // sqrt(1024)

// Grid = 1184 blocks = exactly one wave on 148 SMs at 8 CTAs/SM.
//   blockIdx 0        : doc segmented-count scan (first wave, fully hidden)
//   blockIdx 1..1183  : grid-stride over HALF-TOKEN units.
//
// Work unit = (token t, batch half h): 4 batch rows. 8192 units over 1183
// blocks -> 6.92 units/block, max/mean imbalance 1.012 (vs 1.156 with
// whole-token units in R3). pe row read by 2 blocks; 2nd read is an L2 hit.
#define EW_BLOCKS 1183
#define N_UNITS (S_LEN * 2)

__global__ __launch_bounds__(256, 8)
void pe_fused_kernel(const float4* __restrict__ emb,
                     const int*    __restrict__ src,
                     const float4* __restrict__ pe,
                     float4*       __restrict__ out,
                     float*        __restrict__ doc)
{
    const int blk = blockIdx.x;

    if (blk > 0) {
        const int d = threadIdx.x;           // 0..255
        for (int u = blk - 1; u < N_UNITS; u += EW_BLOCKS) {
            const int t  = u >> 1;
            const int b0 = (u & 1) * 4;
            const float4 p = __ldg(&pe[t * D4 + d]);
            #pragma unroll
            for (int b = b0; b < b0 + 4; b++) {
                const int idx = (t * BATCH + b) * D4 + d;
                float4 e = __ldcs(&emb[idx]);
                float4 o;
                o.x = fmaf(e.x, SCALE, p.x);
                o.y = fmaf(e.y, SCALE, p.y);
                o.z = fmaf(e.z, SCALE, p.z);
                o.w = fmaf(e.w, SCALE, p.w);
                __stcs(&out[idx], o);
            }
        }
        return;
    }

    // ---- doc scan block (blockIdx 0, first wave, overlapped) ----
    __shared__ unsigned words[BATCH * 128];  // 4096 bits per column

    const int warp = threadIdx.x >> 5;       // batch column 0..7
    const int lane = threadIdx.x & 31;

    // Pass 1: build flag bitmasks
    #pragma unroll 8
    for (int c = 0; c < 128; c++) {
        const int t = c * 32 + lane;
        const int v = __ldg(&src[t * BATCH + warp]);
        unsigned m = __ballot_sync(0xFFFFFFFFu, v == SPLIT);
        if (lane == 0) words[warp * 128 + c] = m;
    }
    __syncwarp();

    // Pass 2: inclusive popc-scan with carry; zero positions whose next
    // position is a split token.
    int carry = 0;
    const unsigned le_mask = 0xFFFFFFFFu >> (31 - lane);
    for (int c = 0; c < 128; c++) {
        const unsigned m = words[warp * 128 + c];
        const int t = c * 32 + lane;
        const int incl = carry + __popc(m & le_mask);

        unsigned next_bit;
        if (lane < 31)
            next_bit = (m >> (lane + 1)) & 1u;
        else
            next_bit = (c < 127) ? (words[warp * 128 + c + 1] & 1u) : 0u;

        doc[t * BATCH + warp] = next_bit ? 0.0f : (float)incl;
        carry += __popc(m);
    }
}

extern "C" void kernel_launch(void* const* d_in, const int* in_sizes, int n_in,
                              void* d_out, int out_size)
{
    const float* emb = (const float*)d_in[0];   // [S, B, DIM] f32
    const int*   src = (const int*)  d_in[1];   // [S, B, 1]   i32
    const float* pe  = (const float*)d_in[2];   // [5000, 1, DIM] f32

    float* out = (float*)d_out;                  // first in_sizes[0] floats
    float* doc = out + (size_t)in_sizes[0];      // then S*B floats

    pe_fused_kernel<<<EW_BLOCKS + 1, 256>>>(
        (const float4*)emb, src, (const float4*)pe,
        (float4*)out, doc);
}